// round 2
// baseline (speedup 1.0000x reference)
#include <cuda_runtime.h>

// GaussianRP: x (8,16,32,1024) f32, log_sigma scalar f32
// out (8,16,1024,1024) f32:
//   rp[b,c,t,s] = exp(-max(|x_t|^2+|x_s|^2-2<x_t,x_s>, 0) / (2 sigma^2))
//
// Per-(b,c) Gram matrix via smem-tiled scalar fp32 GEMM (64x64 tile, 4x4
// microtile, K=32 fully resident), exploiting output symmetry: only tile
// pairs (ts <= ss) are computed; each block writes its tile and the
// transposed tile. Squared norms + the scalar exp-scale are precomputed.

#define NB   8
#define NC   16
#define NDIM 32
#define NT   1024
#define NBC  (NB * NC)

#define TILE  64            // output tile edge
#define NTILE (NT / TILE)   // 16 tiles per axis
#define NPAIR (NTILE * (NTILE + 1) / 2)  // 136

__device__ float g_sqnorm[NBC * NT];
__device__ float g_scale;   // 1/(2 sigma^2)

__global__ __launch_bounds__(256)
void norms_kernel(const float* __restrict__ x,
                  const float* __restrict__ log_sigma) {
    int idx = blockIdx.x * blockDim.x + threadIdx.x;   // bc*NT + t
    if (idx == 0) g_scale = 0.5f * __expf(-2.f * log_sigma[0]);
    if (idx >= NBC * NT) return;
    int bc = idx >> 10;
    int t  = idx & (NT - 1);
    const float* p = x + (size_t)bc * NDIM * NT + t;
    float s = 0.f;
#pragma unroll
    for (int d = 0; d < NDIM; ++d) {
        float v = p[d * NT];
        s = fmaf(v, v, s);
    }
    g_sqnorm[idx] = s;
}

__global__ __launch_bounds__(256)
void gaussian_rp_kernel(const float* __restrict__ x,
                        float* __restrict__ out) {
    __shared__ float At[NDIM][TILE];   // t-side tile: [k][t_local]
    __shared__ float As[NDIM][TILE];   // s-side tile: [k][s_local]

    const int bc = blockIdx.x;
    const int p  = blockIdx.y;         // 0..NPAIR-1

    // decode triangular pair index p -> (ts, ss), ts <= ss.
    // p = ss*(ss+1)/2 + ts. Exact integer scan over 16 candidates (cheap,
    // uniform across the block -> no divergence).
    int ss = 0;
#pragma unroll
    for (int c = 1; c < NTILE; ++c)
        ss += (p >= c * (c + 1) / 2) ? 1 : 0;
    const int ts = p - ss * (ss + 1) / 2;

    const int t0 = ts * TILE;
    const int s0 = ss * TILE;

    const int tx  = threadIdx.x;       // 0..15
    const int ty  = threadIdx.y;       // 0..15
    const int tid = ty * 16 + tx;      // 0..255

    // ---- load both 32x64 tiles (float4, fully coalesced) ----
    const float* xb = x + (size_t)bc * NDIM * NT;
    {
        // 32 rows * 16 float4 per tile = 512 float4; 256 threads -> 2 each
#pragma unroll
        for (int r = 0; r < 2; ++r) {
            int lin = tid + 256 * r;       // 0..511
            int d   = lin >> 4;            // row (k)
            int v   = lin & 15;            // float4 index within row
            float4 a = *(const float4*)(xb + d * NT + t0 + v * 4);
            float4 b = *(const float4*)(xb + d * NT + s0 + v * 4);
            *(float4*)&At[d][v * 4] = a;
            *(float4*)&As[d][v * 4] = b;
        }
    }
    __syncthreads();

    // ---- 4x4 microtile over K=32 ----
    float acc[4][4];
#pragma unroll
    for (int i = 0; i < 4; ++i)
#pragma unroll
        for (int j = 0; j < 4; ++j) acc[i][j] = 0.f;

#pragma unroll
    for (int k = 0; k < NDIM; ++k) {
        float4 a = *(const float4*)&At[k][ty * 4];
        float4 b = *(const float4*)&As[k][tx * 4];
        float av[4] = {a.x, a.y, a.z, a.w};
        float bv[4] = {b.x, b.y, b.z, b.w};
#pragma unroll
        for (int i = 0; i < 4; ++i)
#pragma unroll
            for (int j = 0; j < 4; ++j)
                acc[i][j] = fmaf(av[i], bv[j], acc[i][j]);
    }

    // ---- epilogue: d2 -> exp ----
    const float scale = g_scale;

    float nt[4], ns[4];
#pragma unroll
    for (int i = 0; i < 4; ++i) nt[i] = g_sqnorm[bc * NT + t0 + ty * 4 + i];
#pragma unroll
    for (int j = 0; j < 4; ++j) ns[j] = g_sqnorm[bc * NT + s0 + tx * 4 + j];

    float rp[4][4];
#pragma unroll
    for (int i = 0; i < 4; ++i)
#pragma unroll
        for (int j = 0; j < 4; ++j) {
            float d2 = nt[i] + ns[j] - 2.f * acc[i][j];
            d2 = fmaxf(d2, 0.f);
            rp[i][j] = __expf(-d2 * scale);
        }

    float* ob = out + (size_t)bc * NT * NT;

    // normal tile: rows t, cols s (coalesced float4 across tx)
#pragma unroll
    for (int i = 0; i < 4; ++i) {
        int t = t0 + ty * 4 + i;
        float4 v = make_float4(rp[i][0], rp[i][1], rp[i][2], rp[i][3]);
        *(float4*)(ob + (size_t)t * NT + s0 + tx * 4) = v;
    }

    // transposed tile (skip on diagonal blocks): rows s, cols t
    if (ts != ss) {
#pragma unroll
        for (int j = 0; j < 4; ++j) {
            int s = s0 + tx * 4 + j;
            float4 v = make_float4(rp[0][j], rp[1][j], rp[2][j], rp[3][j]);
            *(float4*)(ob + (size_t)s * NT + t0 + ty * 4) = v;
        }
    }
}

extern "C" void kernel_launch(void* const* d_in, const int* in_sizes, int n_in,
                              void* d_out, int out_size) {
    const float* x  = (const float*)d_in[0];
    const float* ls = (const float*)d_in[1];
    float* out      = (float*)d_out;

    norms_kernel<<<(NBC * NT + 255) / 256, 256>>>(x, ls);

    dim3 grid(NBC, NPAIR);
    dim3 block(16, 16);
    gaussian_rp_kernel<<<grid, block>>>(x, out);
}